// round 1
// baseline (speedup 1.0000x reference)
#include <cuda_runtime.h>
#include <math.h>

// Problem constants
#define BB 32
#define LL 512
#define DD 1024
#define MM (BB * LL)   // 16384

// Scratch (no allocations allowed): T = tanh(...) [M,D], mix [M,D]
__device__ float g_T[(size_t)MM * DD];
__device__ float g_mix[(size_t)MM * DD];
__device__ float g_alpha_scratch[(size_t)MM * LL];

// ---------------------------------------------------------------------------
// NT GEMM: C[M,N] = A @ B^T  (A row-major [M,K] ld=K, B row-major [N,K] ld=ldb)
// Optional second source (DUAL): accumulates A1 @ B1^T on top (same K).
// EPI: 0 = none, 1 = tanh(acc + bias0[c] + bias1[c]), 2 = acc + bias0[c]
// Tiles: BM=128, BN=64, BK=16, 256 threads, 8x4 per thread.
// Requires M%128==0, N%64==0, K%16==0 (true for all shapes here).
// ---------------------------------------------------------------------------
template <bool DUAL, int EPI>
__global__ __launch_bounds__(256)
void gemm_nt(const float* __restrict__ A0, const float* __restrict__ A1,
             const float* __restrict__ B0, const float* __restrict__ B1,
             const float* __restrict__ bias0, const float* __restrict__ bias1,
             float* __restrict__ C,
             int M, int N, int K, int ldb, int ldc)
{
    constexpr int BM = 128, BN = 64, BK = 16;
    __shared__ float As[BM][BK + 1];
    __shared__ float Bs[BN][BK + 1];

    const int tid = threadIdx.x;
    const int tx = tid & 15;        // 0..15 -> 4 cols each
    const int ty = tid >> 4;        // 0..15 -> 8 rows each
    const int rowBase = blockIdx.y * BM;
    const int colBase = blockIdx.x * BN;

    const int arow = tid >> 2;      // 0..63
    const int akq  = tid & 3;       // float4 index along K

    float acc[8][4];
#pragma unroll
    for (int i = 0; i < 8; i++)
#pragma unroll
        for (int j = 0; j < 4; j++) acc[i][j] = 0.0f;

    const int ktiles = K / BK;
    const int total  = DUAL ? 2 * ktiles : ktiles;

    for (int kt = 0; kt < total; kt++) {
        const bool second = DUAL && (kt >= ktiles);
        const float* __restrict__ A = second ? A1 : A0;
        const float* __restrict__ Bm = second ? B1 : B0;
        const int k0 = (second ? (kt - ktiles) : kt) * BK;

        // Load A tile: 128x16 = 512 float4, 2 per thread
#pragma unroll
        for (int r = 0; r < 2; r++) {
            const int row = arow + r * 64;
            float4 v = *reinterpret_cast<const float4*>(
                &A[(size_t)(rowBase + row) * K + k0 + akq * 4]);
            As[row][akq * 4 + 0] = v.x;
            As[row][akq * 4 + 1] = v.y;
            As[row][akq * 4 + 2] = v.z;
            As[row][akq * 4 + 3] = v.w;
        }
        // Load B tile: 64x16 = 256 float4, 1 per thread
        {
            float4 v = *reinterpret_cast<const float4*>(
                &Bm[(size_t)(colBase + arow) * ldb + k0 + akq * 4]);
            Bs[arow][akq * 4 + 0] = v.x;
            Bs[arow][akq * 4 + 1] = v.y;
            Bs[arow][akq * 4 + 2] = v.z;
            Bs[arow][akq * 4 + 3] = v.w;
        }
        __syncthreads();

#pragma unroll
        for (int k = 0; k < BK; k++) {
            float a[8], b[4];
#pragma unroll
            for (int i = 0; i < 8; i++) a[i] = As[ty * 8 + i][k];
#pragma unroll
            for (int j = 0; j < 4; j++) b[j] = Bs[tx * 4 + j][k];
#pragma unroll
            for (int i = 0; i < 8; i++)
#pragma unroll
                for (int j = 0; j < 4; j++)
                    acc[i][j] = fmaf(a[i], b[j], acc[i][j]);
        }
        __syncthreads();
    }

#pragma unroll
    for (int i = 0; i < 8; i++) {
        const int r = rowBase + ty * 8 + i;
#pragma unroll
        for (int j = 0; j < 4; j++) {
            const int c = colBase + tx * 4 + j;
            float v = acc[i][j];
            if (EPI == 1) v = tanhf(v + bias0[c] + bias1[c]);
            if (EPI == 2) v = v + bias0[c];
            C[(size_t)r * ldc + c] = v;
        }
    }
}

// ---------------------------------------------------------------------------
// Batched NN GEMM: mix[b] = alpha[b] @ context[b]
// A [512,512] row-major, B [512,1024] row-major, C [512,1024]. 64x64x16 tiles.
// ---------------------------------------------------------------------------
__global__ __launch_bounds__(256)
void gemm_nn_batched(const float* __restrict__ Aall,
                     const float* __restrict__ Ball,
                     float* __restrict__ Call)
{
    constexpr int BM = 64, BN = 64, BK = 16;
    constexpr int Kk = LL, Nn = DD;
    const float* __restrict__ A  = Aall + (size_t)blockIdx.z * LL * LL;
    const float* __restrict__ Bm = Ball + (size_t)blockIdx.z * LL * DD;
    float* __restrict__ C        = Call + (size_t)blockIdx.z * LL * DD;

    __shared__ float As[BM][BK + 1];
    __shared__ float Bs[BK][BN + 4];

    const int tid = threadIdx.x;
    const int tx = tid & 15;
    const int ty = tid >> 4;
    const int rowBase = blockIdx.y * BM;
    const int colBase = blockIdx.x * BN;

    float acc[4][4];
#pragma unroll
    for (int i = 0; i < 4; i++)
#pragma unroll
        for (int j = 0; j < 4; j++) acc[i][j] = 0.0f;

    const int arow = tid >> 2, akq = tid & 3;   // A: 64 rows x 4 float4
    const int brow = tid >> 4, bn = tid & 15;   // B: 16 rows x 16 float4

    for (int k0 = 0; k0 < Kk; k0 += BK) {
        float4 va = *reinterpret_cast<const float4*>(
            &A[(size_t)(rowBase + arow) * Kk + k0 + akq * 4]);
        As[arow][akq * 4 + 0] = va.x;
        As[arow][akq * 4 + 1] = va.y;
        As[arow][akq * 4 + 2] = va.z;
        As[arow][akq * 4 + 3] = va.w;

        float4 vb = *reinterpret_cast<const float4*>(
            &Bm[(size_t)(k0 + brow) * Nn + colBase + bn * 4]);
        *reinterpret_cast<float4*>(&Bs[brow][bn * 4]) = vb;  // row stride 68 floats: 16B aligned
        __syncthreads();

#pragma unroll
        for (int k = 0; k < BK; k++) {
            float a[4], b[4];
#pragma unroll
            for (int i = 0; i < 4; i++) a[i] = As[ty * 4 + i][k];
#pragma unroll
            for (int j = 0; j < 4; j++) b[j] = Bs[k][tx * 4 + j];
#pragma unroll
            for (int i = 0; i < 4; i++)
#pragma unroll
                for (int j = 0; j < 4; j++)
                    acc[i][j] = fmaf(a[i], b[j], acc[i][j]);
        }
        __syncthreads();
    }

#pragma unroll
    for (int i = 0; i < 4; i++) {
        const int r = rowBase + ty * 4 + i;
#pragma unroll
        for (int j = 0; j < 4; j++)
            C[(size_t)r * Nn + colBase + tx * 4 + j] = acc[i][j];
    }
}

// ---------------------------------------------------------------------------
// In-place row softmax over 512 elements. 128 threads, 4 elems/thread (float4).
// ---------------------------------------------------------------------------
__global__ __launch_bounds__(128)
void softmax512(float* __restrict__ X)
{
    const int row = blockIdx.x;
    const int t = threadIdx.x;
    const int lane = t & 31, wid = t >> 5;
    __shared__ float red[4];

    float4 v = *reinterpret_cast<float4*>(&X[(size_t)row * LL + t * 4]);

    // max
    float m = fmaxf(fmaxf(v.x, v.y), fmaxf(v.z, v.w));
#pragma unroll
    for (int off = 16; off > 0; off >>= 1)
        m = fmaxf(m, __shfl_xor_sync(0xffffffffu, m, off));
    if (lane == 0) red[wid] = m;
    __syncthreads();
    const float rm = fmaxf(fmaxf(red[0], red[1]), fmaxf(red[2], red[3]));
    __syncthreads();

    v.x = __expf(v.x - rm);
    v.y = __expf(v.y - rm);
    v.z = __expf(v.z - rm);
    v.w = __expf(v.w - rm);

    // sum
    float s = v.x + v.y + v.z + v.w;
#pragma unroll
    for (int off = 16; off > 0; off >>= 1)
        s += __shfl_xor_sync(0xffffffffu, s, off);
    if (lane == 0) red[wid] = s;
    __syncthreads();
    const float inv = 1.0f / (red[0] + red[1] + red[2] + red[3]);

    v.x *= inv; v.y *= inv; v.z *= inv; v.w *= inv;
    *reinterpret_cast<float4*>(&X[(size_t)row * LL + t * 4]) = v;
}

// ---------------------------------------------------------------------------
// Launcher
// Inputs (metadata order): query, context, W_in, b_in, W_in2, b_in2, W_out,
//                          W_fc, b_fc.  Output: [out (M*D) | alpha (M*L)] fp32.
// ---------------------------------------------------------------------------
extern "C" void kernel_launch(void* const* d_in, const int* in_sizes, int n_in,
                              void* d_out, int out_size)
{
    const float* query   = (const float*)d_in[0];
    const float* context = (const float*)d_in[1];
    const float* W_in    = (const float*)d_in[2];
    const float* b_in    = (const float*)d_in[3];
    const float* W_in2   = (const float*)d_in[4];
    const float* b_in2   = (const float*)d_in[5];
    const float* W_out   = (const float*)d_in[6];
    const float* W_fc    = (const float*)d_in[7];
    const float* b_fc    = (const float*)d_in[8];

    float* out = (float*)d_out;

    // alpha lives in d_out right after `out` when the harness expects both
    // reference outputs; otherwise fall back to scratch.
    float* T;   cudaGetSymbolAddress((void**)&T, g_T);          // graph-safe (host-side query)
    float* mix; cudaGetSymbolAddress((void**)&mix, g_mix);
    float* alphaFallback; cudaGetSymbolAddress((void**)&alphaFallback, g_alpha_scratch);
    float* alpha = ((size_t)out_size >= (size_t)MM * (DD + LL))
                       ? out + (size_t)MM * DD
                       : alphaFallback;

    // 1) T = tanh(query@W_in^T + context@W_in2^T + b_in + b_in2)   [M, D]
    gemm_nt<true, 1><<<dim3(DD / 64, MM / 128), 256>>>(
        query, context, W_in, W_in2, b_in, b_in2, T, MM, DD, DD, DD, DD);

    // 2) logits = T @ W_out^T   [M, L]  (into alpha region)
    gemm_nt<false, 0><<<dim3(LL / 64, MM / 128), 256>>>(
        T, nullptr, W_out, nullptr, nullptr, nullptr, alpha, MM, LL, DD, DD, LL);

    // 3) softmax rows
    softmax512<<<MM, 128>>>(alpha);

    // 4) mix[b] = alpha[b] @ context[b]   [B, L, D]
    gemm_nn_batched<<<dim3(DD / 64, LL / 64, BB), 256>>>(alpha, context, mix);

    // 5) out = mix @ W_fc[:, :D]^T + context @ W_fc[:, D:]^T + b_fc
    gemm_nt<true, 2><<<dim3(DD / 64, MM / 128), 256>>>(
        mix, context, W_fc, W_fc + DD, b_fc, nullptr, out, MM, DD, DD, 2 * DD, DD);
}

// round 4
// speedup vs baseline: 2.7110x; 2.7110x over previous
#include <cuda_runtime.h>
#include <cuda_bf16.h>
#include <math.h>
#include <stdint.h>

// Problem constants
#define BB 32
#define LL 512
#define DD 1024
#define MM (BB * LL)   // 16384

// Scratch (no allocations allowed)
__device__ float g_T[(size_t)MM * DD];
__device__ float g_mix[(size_t)MM * DD];
__device__ float g_alpha_scratch[(size_t)MM * LL];

// ---------------------------------------------------------------------------
// Helpers
// ---------------------------------------------------------------------------
__device__ __forceinline__ uint32_t smem_u32(const void* p) {
    uint32_t a;
    asm("{ .reg .u64 t; cvta.to.shared.u64 t, %1; cvt.u32.u64 %0, t; }" : "=r"(a) : "l"(p));
    return a;
}
// pack: low16 = bf16(x), high16 = bf16(y)
__device__ __forceinline__ uint32_t pack_bf16x2(float x, float y) {
    uint32_t r;
    asm("cvt.rn.bf16x2.f32 %0, %1, %2;" : "=r"(r) : "f"(y), "f"(x));
    return r;
}
__device__ __forceinline__ void ldsm_x4(uint32_t& r0, uint32_t& r1, uint32_t& r2, uint32_t& r3,
                                        uint32_t addr) {
    asm volatile("ldmatrix.sync.aligned.m8n8.x4.shared.b16 {%0,%1,%2,%3}, [%4];"
                 : "=r"(r0), "=r"(r1), "=r"(r2), "=r"(r3) : "r"(addr));
}
__device__ __forceinline__ void ldsm_x4t(uint32_t& r0, uint32_t& r1, uint32_t& r2, uint32_t& r3,
                                         uint32_t addr) {
    asm volatile("ldmatrix.sync.aligned.m8n8.x4.trans.shared.b16 {%0,%1,%2,%3}, [%4];"
                 : "=r"(r0), "=r"(r1), "=r"(r2), "=r"(r3) : "r"(addr));
}
__device__ __forceinline__ void mma_bf16(float* d, const uint32_t* a, const uint32_t* b) {
    asm volatile(
        "mma.sync.aligned.m16n8k16.row.col.f32.bf16.bf16.f32 "
        "{%0,%1,%2,%3}, {%4,%5,%6,%7}, {%8,%9}, {%0,%1,%2,%3};"
        : "+f"(d[0]), "+f"(d[1]), "+f"(d[2]), "+f"(d[3])
        : "r"(a[0]), "r"(a[1]), "r"(a[2]), "r"(a[3]), "r"(b[0]), "r"(b[1]));
}

// ---------------------------------------------------------------------------
// SMEM layout per stage (bytes):
//   As_hi [128][40]bf16 @ 0       (10240)
//   As_lo [128][40]bf16 @ 10240
//   Bs_hi              @ 20480    (NT: [128][40]bf16 ; NN-trans: [32][136]bf16)
//   Bs_lo              @ 30720
// Stage = 40960, double buffered -> 81920 dynamic SMEM.
// ---------------------------------------------------------------------------
static constexpr int STAGE = 40960;
static constexpr int SMEM_TOTAL = 2 * STAGE;
static constexpr int A_ROW_B = 80;    // 40 bf16 per row
static constexpr int BT_ROW_B = 272;  // 136 bf16 per row (trans layout)

// ---------------------------------------------------------------------------
// Split-bf16 tensor-core GEMM (mma.sync): C = A0@B0^T (+ A1@B1^T if DUAL)
// A row-major [M,K] ld=lda. NT: B row-major [N,K] ld=ldb. BTRANS: B [K,N] ld=ldb.
// Tiles: BM=128, BN=128, BK=32. 256 threads. EPI: 0 none, 1 tanh(+b0+b1), 2 +b0.
// ---------------------------------------------------------------------------
template <bool DUAL, bool BTRANS, int EPI>
__global__ __launch_bounds__(256, 1)
void tc_gemm(const float* __restrict__ A0, const float* __restrict__ A1,
             const float* __restrict__ B0, const float* __restrict__ B1,
             const float* __restrict__ bias0, const float* __restrict__ bias1,
             float* __restrict__ C,
             int K, int lda, int ldb, int ldc,
             long sA, long sB, long sC)
{
    extern __shared__ char smem[];
    const uint32_t sb = smem_u32(smem);
    const int tid = threadIdx.x;
    const int wid = tid >> 5;
    const int lane = tid & 31;
    const int wm = wid >> 2;          // 0..1 : 64 rows each
    const int wn = wid & 3;           // 0..3 : 32 cols each
    const int rowBase = blockIdx.y * 128;
    const int colBase = blockIdx.x * 128;
    const long z = blockIdx.z;

    const int kc = K / 32;
    const int C_CH = DUAL ? 2 * kc : kc;

    float acc[4][4][4];               // [mt][nt][reg]
#pragma unroll
    for (int i = 0; i < 4; i++)
#pragma unroll
        for (int j = 0; j < 4; j++)
#pragma unroll
            for (int r = 0; r < 4; r++) acc[i][j][r] = 0.f;

    // Global staging indices
    const int arow0 = tid >> 3, akq = tid & 7;    // A: 32 rows/iter x 8 float4
    const int btk0 = tid >> 5, btn = tid & 31;    // B-trans: 8 k/iter x 32 float4

    float4 ar[4], br[4];

    auto ldgChunk = [&](int c) {
        const float* aS = (!DUAL || c < kc) ? A0 : A1;
        const float* bS = (!DUAL || c < kc) ? B0 : B1;
        const int k0 = ((!DUAL || c < kc) ? c : c - kc) * 32;
        const float* aT = aS + z * sA;
        const float* bT = bS + z * sB;
#pragma unroll
        for (int it = 0; it < 4; it++) {
            const int row = arow0 + it * 32;
            ar[it] = *reinterpret_cast<const float4*>(
                aT + (size_t)(rowBase + row) * lda + k0 + akq * 4);
        }
        if (BTRANS) {
#pragma unroll
            for (int it = 0; it < 4; it++) {
                const int k = btk0 + it * 8;
                br[it] = *reinterpret_cast<const float4*>(
                    bT + (size_t)(k0 + k) * ldb + colBase + btn * 4);
            }
        } else {
#pragma unroll
            for (int it = 0; it < 4; it++) {
                const int row = arow0 + it * 32;
                br[it] = *reinterpret_cast<const float4*>(
                    bT + (size_t)(colBase + row) * ldb + k0 + akq * 4);
            }
        }
    };

    auto stsSplit8 = [&](char* hiP, char* loP, float4 v) {
        uint32_t h0 = pack_bf16x2(v.x, v.y);
        uint32_t h1 = pack_bf16x2(v.z, v.w);
        float hx = __uint_as_float(h0 << 16);
        float hy = __uint_as_float(h0 & 0xffff0000u);
        float hz = __uint_as_float(h1 << 16);
        float hw = __uint_as_float(h1 & 0xffff0000u);
        uint32_t l0 = pack_bf16x2(v.x - hx, v.y - hy);
        uint32_t l1 = pack_bf16x2(v.z - hz, v.w - hw);
        *reinterpret_cast<uint2*>(hiP) = make_uint2(h0, h1);
        *reinterpret_cast<uint2*>(loP) = make_uint2(l0, l1);
    };

    auto stsChunk = [&](int s) {
        char* base = smem + s * STAGE;
#pragma unroll
        for (int it = 0; it < 4; it++) {
            const int row = arow0 + it * 32;
            stsSplit8(base + row * A_ROW_B + akq * 8,
                      base + 10240 + row * A_ROW_B + akq * 8, ar[it]);
        }
        if (BTRANS) {
#pragma unroll
            for (int it = 0; it < 4; it++) {
                const int k = btk0 + it * 8;
                stsSplit8(base + 20480 + k * BT_ROW_B + btn * 8,
                          base + 30720 + k * BT_ROW_B + btn * 8, br[it]);
            }
        } else {
#pragma unroll
            for (int it = 0; it < 4; it++) {
                const int row = arow0 + it * 32;
                stsSplit8(base + 20480 + row * A_ROW_B + akq * 8,
                          base + 30720 + row * A_ROW_B + akq * 8, br[it]);
            }
        }
    };

    auto computeChunk = [&](int s) {
        const uint32_t base = sb + s * STAGE;
#pragma unroll
        for (int ks = 0; ks < 2; ks++) {
            uint32_t ah[4][4], al[4][4], bh[4][2], bl[4][2];
            // A fragments: 4 m-tiles, hi + lo
#pragma unroll
            for (int mt = 0; mt < 4; mt++) {
                const int row = wm * 64 + mt * 16 + (lane & 15);
                const uint32_t off = row * A_ROW_B + ks * 32 + (lane >> 4) * 16;
                ldsm_x4(ah[mt][0], ah[mt][1], ah[mt][2], ah[mt][3], base + off);
                ldsm_x4(al[mt][0], al[mt][1], al[mt][2], al[mt][3], base + 10240 + off);
            }
            // B fragments: 2 pairs covering 4 n-tiles, hi + lo
#pragma unroll
            for (int p = 0; p < 2; p++) {
                uint32_t q0, q1, q2, q3;
                if (BTRANS) {
                    const int k = ks * 16 + (lane & 15);
                    const int nc = wn * 32 + p * 16 + (lane >> 4) * 8;
                    const uint32_t off = k * BT_ROW_B + nc * 2;
                    ldsm_x4t(q0, q1, q2, q3, base + 20480 + off);
                    bh[2 * p][0] = q0; bh[2 * p][1] = q1;
                    bh[2 * p + 1][0] = q2; bh[2 * p + 1][1] = q3;
                    ldsm_x4t(q0, q1, q2, q3, base + 30720 + off);
                    bl[2 * p][0] = q0; bl[2 * p][1] = q1;
                    bl[2 * p + 1][0] = q2; bl[2 * p + 1][1] = q3;
                } else {
                    const int row = wn * 32 + p * 16 + (lane & 15);
                    const uint32_t off = row * A_ROW_B + ks * 32 + (lane >> 4) * 16;
                    ldsm_x4(q0, q1, q2, q3, base + 20480 + off);
                    bh[2 * p][0] = q0; bh[2 * p][1] = q2;
                    bh[2 * p + 1][0] = q1; bh[2 * p + 1][1] = q3;
                    ldsm_x4(q0, q1, q2, q3, base + 30720 + off);
                    bl[2 * p][0] = q0; bl[2 * p][1] = q2;
                    bl[2 * p + 1][0] = q1; bl[2 * p + 1][1] = q3;
                }
            }
#pragma unroll
            for (int mt = 0; mt < 4; mt++)
#pragma unroll
                for (int nt = 0; nt < 4; nt++) {
                    mma_bf16(acc[mt][nt], ah[mt], bh[nt]);   // hi*hi
                    mma_bf16(acc[mt][nt], ah[mt], bl[nt]);   // hi*lo
                    mma_bf16(acc[mt][nt], al[mt], bh[nt]);   // lo*hi
                }
        }
    };

    // Software pipeline: LDG(c+1) | compute(c) | STS(c+1)
    ldgChunk(0);
    stsChunk(0);
    __syncthreads();
    for (int c = 0; c < C_CH; ++c) {
        const int s = c & 1;
        if (c + 1 < C_CH) ldgChunk(c + 1);
        computeChunk(s);
        __syncthreads();
        if (c + 1 < C_CH) {
            stsChunk(s ^ 1);
            __syncthreads();
        }
    }

    // Epilogue: acc[mt][nt] regs -> C
    const int lr = lane >> 2, lc = (lane & 3) * 2;
#pragma unroll
    for (int mt = 0; mt < 4; mt++) {
        const int r0 = rowBase + wm * 64 + mt * 16 + lr;
#pragma unroll
        for (int nt = 0; nt < 4; nt++) {
            const int c0 = colBase + wn * 32 + nt * 8 + lc;
            float v0 = acc[mt][nt][0], v1 = acc[mt][nt][1];
            float v2 = acc[mt][nt][2], v3 = acc[mt][nt][3];
            if (EPI == 1) {
                const float s0 = bias0[c0] + bias1[c0];
                const float s1 = bias0[c0 + 1] + bias1[c0 + 1];
                v0 = tanhf(v0 + s0); v1 = tanhf(v1 + s1);
                v2 = tanhf(v2 + s0); v3 = tanhf(v3 + s1);
            }
            if (EPI == 2) {
                v0 += bias0[c0]; v1 += bias0[c0 + 1];
                v2 += bias0[c0]; v3 += bias0[c0 + 1];
            }
            float* p0 = C + z * sC + (size_t)r0 * ldc + c0;
            *reinterpret_cast<float2*>(p0) = make_float2(v0, v1);
            *reinterpret_cast<float2*>(p0 + 8 * ldc) = make_float2(v2, v3);
        }
    }
}

// ---------------------------------------------------------------------------
// In-place row softmax over 512 elements. 128 threads, float4.
// ---------------------------------------------------------------------------
__global__ __launch_bounds__(128)
void softmax512(float* __restrict__ X)
{
    const int row = blockIdx.x;
    const int t = threadIdx.x;
    const int lane = t & 31, wd = t >> 5;
    __shared__ float red[4];

    float4 v = *reinterpret_cast<float4*>(&X[(size_t)row * LL + t * 4]);

    float m = fmaxf(fmaxf(v.x, v.y), fmaxf(v.z, v.w));
#pragma unroll
    for (int off = 16; off > 0; off >>= 1)
        m = fmaxf(m, __shfl_xor_sync(0xffffffffu, m, off));
    if (lane == 0) red[wd] = m;
    __syncthreads();
    const float rm = fmaxf(fmaxf(red[0], red[1]), fmaxf(red[2], red[3]));
    __syncthreads();

    v.x = __expf(v.x - rm); v.y = __expf(v.y - rm);
    v.z = __expf(v.z - rm); v.w = __expf(v.w - rm);

    float s = v.x + v.y + v.z + v.w;
#pragma unroll
    for (int off = 16; off > 0; off >>= 1)
        s += __shfl_xor_sync(0xffffffffu, s, off);
    if (lane == 0) red[wd] = s;
    __syncthreads();
    const float inv = 1.0f / (red[0] + red[1] + red[2] + red[3]);

    v.x *= inv; v.y *= inv; v.z *= inv; v.w *= inv;
    *reinterpret_cast<float4*>(&X[(size_t)row * LL + t * 4]) = v;
}

// ---------------------------------------------------------------------------
// Launcher
// ---------------------------------------------------------------------------
extern "C" void kernel_launch(void* const* d_in, const int* in_sizes, int n_in,
                              void* d_out, int out_size)
{
    const float* query   = (const float*)d_in[0];
    const float* context = (const float*)d_in[1];
    const float* W_in    = (const float*)d_in[2];
    const float* b_in    = (const float*)d_in[3];
    const float* W_in2   = (const float*)d_in[4];
    const float* b_in2   = (const float*)d_in[5];
    const float* W_out   = (const float*)d_in[6];
    const float* W_fc    = (const float*)d_in[7];
    const float* b_fc    = (const float*)d_in[8];

    float* out = (float*)d_out;

    float* T;   cudaGetSymbolAddress((void**)&T, g_T);
    float* mix; cudaGetSymbolAddress((void**)&mix, g_mix);
    float* alphaFallback; cudaGetSymbolAddress((void**)&alphaFallback, g_alpha_scratch);
    float* alpha = ((size_t)out_size >= (size_t)MM * (DD + LL))
                       ? out + (size_t)MM * DD
                       : alphaFallback;

    cudaFuncSetAttribute(tc_gemm<true,  false, 1>, cudaFuncAttributeMaxDynamicSharedMemorySize, SMEM_TOTAL);
    cudaFuncSetAttribute(tc_gemm<false, false, 0>, cudaFuncAttributeMaxDynamicSharedMemorySize, SMEM_TOTAL);
    cudaFuncSetAttribute(tc_gemm<false, true,  0>, cudaFuncAttributeMaxDynamicSharedMemorySize, SMEM_TOTAL);
    cudaFuncSetAttribute(tc_gemm<true,  false, 2>, cudaFuncAttributeMaxDynamicSharedMemorySize, SMEM_TOTAL);

    // 1) T = tanh(query@W_in^T + context@W_in2^T + b_in + b_in2)   [M, D]
    tc_gemm<true, false, 1><<<dim3(DD / 128, MM / 128, 1), 256, SMEM_TOTAL>>>(
        query, context, W_in, W_in2, b_in, b_in2, T,
        DD, DD, DD, DD, 0, 0, 0);

    // 2) logits = T @ W_out^T   [M, L]
    tc_gemm<false, false, 0><<<dim3(LL / 128, MM / 128, 1), 256, SMEM_TOTAL>>>(
        T, nullptr, W_out, nullptr, nullptr, nullptr, alpha,
        DD, DD, DD, LL, 0, 0, 0);

    // 3) softmax rows
    softmax512<<<MM, 128>>>(alpha);

    // 4) mix[b] = alpha[b] @ context[b]   [B, L, D]  (NN, batched)
    tc_gemm<false, true, 0><<<dim3(DD / 128, LL / 128, BB), 256, SMEM_TOTAL>>>(
        alpha, nullptr, context, nullptr, nullptr, nullptr, mix,
        LL, LL, DD, DD, (long)LL * LL, (long)LL * DD, (long)LL * DD);

    // 5) out = mix @ W_fc[:, :D]^T + context @ W_fc[:, D:]^T + b_fc
    tc_gemm<true, false, 2><<<dim3(DD / 128, MM / 128, 1), 256, SMEM_TOTAL>>>(
        mix, context, W_fc, W_fc + DD, b_fc, nullptr, out,
        DD, DD, 2 * DD, DD, 0, 0, 0);
}